// round 2
// baseline (speedup 1.0000x reference)
#include <cuda_runtime.h>
#include <math.h>

#define NPOS 16384
#define NPOS_MASK 16383
#define RWC 512
#define SWC 256
#define CDC 16

// Persistent scratch (allocation-free rule: __device__ globals)
__device__ float g_feat [RWC * NPOS];   // 33.5 MB
__device__ float g_res  [RWC * NPOS];   // 33.5 MB
__device__ float g_skip [SWC * NPOS];   // 16.8 MB
__device__ float g_skip2[SWC * NPOS];   // 16.8 MB
__device__ float g_xl   [NPOS];
__device__ float g_cond [CDC * NPOS];

// ---------------------------------------------------------------------------
// Repack x (B,1,W) and cond (B,16,W) into L-layout: L = w*4 + b
// ---------------------------------------------------------------------------
__global__ void repack_kernel(const float* __restrict__ x,
                              const float* __restrict__ cond)
{
    int idx = blockIdx.x * blockDim.x + threadIdx.x;
    if (idx >= 17 * NPOS) return;
    int j = idx >> 14;            // 0..15 = cond channel, 16 = x
    int L = idx & NPOS_MASK;
    int b = L & 3, w = L >> 2;
    if (j == 16) g_xl[L] = x[b * 4096 + w];
    else         g_cond[j * NPOS + L] = cond[(b * CDC + j) * 4096 + w];
}

// ---------------------------------------------------------------------------
// Init conv: feat[c][L] = init_b[c] + sum_t init_w[c][t] * x[L + (t-1)*4]
// ---------------------------------------------------------------------------
__global__ void init_conv_kernel(const float* __restrict__ iw,
                                 const float* __restrict__ ib)
{
    int idx = blockIdx.x * blockDim.x + threadIdx.x;   // over 512*16384
    int c = idx >> 14;
    int L = idx & NPOS_MASK;
    float acc = ib[c];
    acc = fmaf(iw[c * 3 + 1], g_xl[L], acc);
    if (L >= 4)        acc = fmaf(iw[c * 3 + 0], g_xl[L - 4], acc);
    if (L < NPOS - 4)  acc = fmaf(iw[c * 3 + 2], g_xl[L + 4], acc);
    g_feat[idx] = acc;
}

// ---------------------------------------------------------------------------
// Generic tiled GEMM: C[M x NPOS] (+)= A[M x K] * B[K x NPOS] (+ bias)
// 64x64 tile, 256 threads, 4x4 register tile per thread.
// RELU_IN: relu applied to B on load. ACC: C += (bias ignored).
// TOUT: store to (B,256,W)-ordered output.
// ---------------------------------------------------------------------------
template<int RELU_IN, int ACC, int TOUT>
__global__ void __launch_bounds__(256) gemm64_kernel(
    const float* __restrict__ A, const float* __restrict__ Bm,
    float* __restrict__ C, const float* __restrict__ bias, int K)
{
    __shared__ float sA[64 * 16];   // [m][k]
    __shared__ float sB[16 * 64];   // [k][n]
    int tid = threadIdx.x;
    int tx = tid & 15, ty = tid >> 4;
    int L0 = blockIdx.x * 64;
    int m0 = blockIdx.y * 64;
    float acc[4][4] = {};

    for (int k0 = 0; k0 < K; k0 += 16) {
        {   // A tile: thread loads one float4 (row m, 4 consecutive k)
            int m = tid >> 2, kk = (tid & 3) << 2;
            *(float4*)(sA + m * 16 + kk) =
                *(const float4*)(A + (size_t)(m0 + m) * K + k0 + kk);
        }
        {   // B tile
            int kk = tid >> 4, n = (tid & 15) << 2;
            float4 v = *(const float4*)(Bm + (size_t)(k0 + kk) * NPOS + L0 + n);
            if (RELU_IN) {
                v.x = fmaxf(v.x, 0.f); v.y = fmaxf(v.y, 0.f);
                v.z = fmaxf(v.z, 0.f); v.w = fmaxf(v.w, 0.f);
            }
            *(float4*)(sB + kk * 64 + n) = v;
        }
        __syncthreads();
        #pragma unroll
        for (int kk = 0; kk < 16; kk++) {
            float4 b4 = *(float4*)(sB + kk * 64 + (tx << 2));
            float bx[4] = {b4.x, b4.y, b4.z, b4.w};
            #pragma unroll
            for (int j = 0; j < 4; j++) {
                float a = sA[(ty * 4 + j) * 16 + kk];
                #pragma unroll
                for (int i = 0; i < 4; i++)
                    acc[j][i] = fmaf(a, bx[i], acc[j][i]);
            }
        }
        __syncthreads();
    }

    #pragma unroll
    for (int j = 0; j < 4; j++) {
        int m = m0 + ty * 4 + j;
        int L = L0 + (tx << 2);
        if (ACC) {
            float4* p = (float4*)(C + (size_t)m * NPOS + L);
            float4 v = *p;
            v.x += acc[j][0]; v.y += acc[j][1];
            v.z += acc[j][2]; v.w += acc[j][3];
            *p = v;
        } else {
            float bv = (bias != nullptr) ? bias[m] : 0.f;
            if (TOUT) {
                #pragma unroll
                for (int i = 0; i < 4; i++) {
                    int Li = L + i;
                    int b = Li & 3, w = Li >> 2;
                    C[((size_t)b * SWC + m) * 4096 + w] = acc[j][i] + bv;
                }
            } else {
                float4 v;
                v.x = acc[j][0] + bv; v.y = acc[j][1] + bv;
                v.z = acc[j][2] + bv; v.w = acc[j][3] + bv;
                *(float4*)(C + (size_t)m * NPOS + L) = v;
            }
        }
    }
}

// ---------------------------------------------------------------------------
// Fused accumulate GEMM for one layer:
//   blocks with blockIdx.y <  8 : g_feat += feat_w @ g_res   (rows 0..511)
//   blocks with blockIdx.y >= 8 : g_skip += skip_w @ g_res   (rows 0..255)
// Same 64x64x16 tiling as gemm64_kernel, K = 512 fixed.
// ---------------------------------------------------------------------------
__global__ void __launch_bounds__(256) accum2_kernel(
    const float* __restrict__ Wfeat, const float* __restrict__ Wskip)
{
    __shared__ float sA[64 * 16];
    __shared__ float sB[16 * 64];
    int tid = threadIdx.x;
    int tx = tid & 15, ty = tid >> 4;
    int L0 = blockIdx.x * 64;
    int by = blockIdx.y;
    const float* A;
    float* C;
    int m0;
    if (by < 8) { A = Wfeat; C = g_feat; m0 = by * 64; }
    else        { A = Wskip; C = g_skip; m0 = (by - 8) * 64; }
    float acc[4][4] = {};

    for (int k0 = 0; k0 < RWC; k0 += 16) {
        {
            int m = tid >> 2, kk = (tid & 3) << 2;
            *(float4*)(sA + m * 16 + kk) =
                *(const float4*)(A + (size_t)(m0 + m) * RWC + k0 + kk);
        }
        {
            int kk = tid >> 4, n = (tid & 15) << 2;
            *(float4*)(sB + kk * 64 + n) =
                *(const float4*)(g_res + (size_t)(k0 + kk) * NPOS + L0 + n);
        }
        __syncthreads();
        #pragma unroll
        for (int kk = 0; kk < 16; kk++) {
            float4 b4 = *(float4*)(sB + kk * 64 + (tx << 2));
            float bx[4] = {b4.x, b4.y, b4.z, b4.w};
            #pragma unroll
            for (int j = 0; j < 4; j++) {
                float a = sA[(ty * 4 + j) * 16 + kk];
                #pragma unroll
                for (int i = 0; i < 4; i++)
                    acc[j][i] = fmaf(a, bx[i], acc[j][i]);
            }
        }
        __syncthreads();
    }

    #pragma unroll
    for (int j = 0; j < 4; j++) {
        int m = m0 + ty * 4 + j;
        int L = L0 + (tx << 2);
        float4* p = (float4*)(C + (size_t)m * NPOS + L);
        float4 v = *p;
        v.x += acc[j][0]; v.y += acc[j][1];
        v.z += acc[j][2]; v.w += acc[j][3];
        *p = v;
    }
}

// ---------------------------------------------------------------------------
// Layer residual kernel: fused filter+gate dilated conv + cond + gated act.
// K dimension = 512 channels x 3 taps (chunked 16 ch = 48 kk) + 16 cond ch.
// Tap t reads feat[c][L + (t-1)*sh], sh = 4*d; OOB -> 0 (== conv padding).
// ---------------------------------------------------------------------------
__global__ void __launch_bounds__(256) layer_res_kernel(
    const float* __restrict__ Wf, const float* __restrict__ Wg,
    const float* __restrict__ Wfc, const float* __restrict__ Wgc,
    int sh)
{
    __shared__ float sWf[64 * 48];  // [m][kk], kk = c_local*3 + t
    __shared__ float sWg[64 * 48];
    __shared__ float sX [48 * 64];  // [kk][n]
    int tid = threadIdx.x;
    int tx = tid & 15, ty = tid >> 4;
    int L0 = blockIdx.x * 64;
    int o0 = blockIdx.y * 64;
    float af[4][4] = {};
    float ag[4][4] = {};

    for (int c0 = 0; c0 < RWC; c0 += 16) {
        // weights: 64 rows x 48 (contiguous 48-float run per output channel)
        #pragma unroll
        for (int r = 0; r < 3; r++) {
            int e = tid + r * 256;         // float4 index 0..767
            int m = e / 12;
            int kk = (e - m * 12) * 4;
            size_t off = (size_t)(o0 + m) * 1536 + c0 * 3 + kk;
            *(float4*)(sWf + m * 48 + kk) = *(const float4*)(Wf + off);
            *(float4*)(sWg + m * 48 + kk) = *(const float4*)(Wg + off);
        }
        // X: 48 rows x 64, row kk=(cl,t) is feat[c0+cl] shifted by (t-1)*sh
        #pragma unroll
        for (int r = 0; r < 3; r++) {
            int e = tid + r * 256;
            int kk = e >> 4;
            int n4 = (e & 15) << 2;
            int cl = kk / 3;
            int t  = kk - cl * 3;
            int pos = L0 + n4 + (t - 1) * sh;
            float4 v = make_float4(0.f, 0.f, 0.f, 0.f);
            if (pos >= 0 && pos < NPOS)
                v = *(const float4*)(g_feat + (size_t)(c0 + cl) * NPOS + pos);
            *(float4*)(sX + kk * 64 + n4) = v;
        }
        __syncthreads();
        #pragma unroll 8
        for (int kk = 0; kk < 48; kk++) {
            float4 b4 = *(float4*)(sX + kk * 64 + (tx << 2));
            float bx[4] = {b4.x, b4.y, b4.z, b4.w};
            #pragma unroll
            for (int j = 0; j < 4; j++) {
                float wf = sWf[(ty * 4 + j) * 48 + kk];
                float wg = sWg[(ty * 4 + j) * 48 + kk];
                #pragma unroll
                for (int i = 0; i < 4; i++) {
                    af[j][i] = fmaf(wf, bx[i], af[j][i]);
                    ag[j][i] = fmaf(wg, bx[i], ag[j][i]);
                }
            }
        }
        __syncthreads();
    }

    // cond contribution: 16 extra K rows (center tap only, no shift)
    {
        int m = tid >> 2, kk = (tid & 3) << 2;
        *(float4*)(sWf + m * 16 + kk) = *(const float4*)(Wfc + (size_t)(o0 + m) * 16 + kk);
        *(float4*)(sWg + m * 16 + kk) = *(const float4*)(Wgc + (size_t)(o0 + m) * 16 + kk);
        int kb = tid >> 4, n = (tid & 15) << 2;
        *(float4*)(sX + kb * 64 + n) = *(const float4*)(g_cond + (size_t)kb * NPOS + L0 + n);
    }
    __syncthreads();
    #pragma unroll
    for (int kk = 0; kk < 16; kk++) {
        float4 b4 = *(float4*)(sX + kk * 64 + (tx << 2));
        float bx[4] = {b4.x, b4.y, b4.z, b4.w};
        #pragma unroll
        for (int j = 0; j < 4; j++) {
            float wf = sWf[(ty * 4 + j) * 16 + kk];
            float wg = sWg[(ty * 4 + j) * 16 + kk];
            #pragma unroll
            for (int i = 0; i < 4; i++) {
                af[j][i] = fmaf(wf, bx[i], af[j][i]);
                ag[j][i] = fmaf(wg, bx[i], ag[j][i]);
            }
        }
    }

    // epilogue: residual = sigmoid(f) * tanh(g)
    #pragma unroll
    for (int j = 0; j < 4; j++) {
        int o = o0 + ty * 4 + j;
        float4 v;
        float* vv = &v.x;
        #pragma unroll
        for (int i = 0; i < 4; i++) {
            float f = af[j][i], g = ag[j][i];
            float s = 1.f / (1.f + expf(-f));
            vv[i] = s * tanhf(g);
        }
        *(float4*)(g_res + (size_t)o * NPOS + L0 + (tx << 2)) = v;
    }
}

// ---------------------------------------------------------------------------
extern "C" void kernel_launch(void* const* d_in, const int* in_sizes, int n_in,
                              void* d_out, int out_size)
{
    const float* x           = (const float*)d_in[0];
    const float* cond        = (const float*)d_in[1];
    const float* init_w      = (const float*)d_in[2];
    const float* init_b      = (const float*)d_in[3];
    const float* init_skip_w = (const float*)d_in[4];
    const float* init_skip_b = (const float*)d_in[5];
    const float* filter_w    = (const float*)d_in[6];
    const float* gate_w      = (const float*)d_in[7];
    const float* skip_w      = (const float*)d_in[8];
    const float* feat_w      = (const float*)d_in[9];
    const float* fcond_w     = (const float*)d_in[10];
    const float* gcond_w     = (const float*)d_in[11];
    const float* fsw         = (const float*)d_in[12];
    const float* fsb         = (const float*)d_in[13];
    const float* fw          = (const float*)d_in[14];
    const float* fb          = (const float*)d_in[15];

    float *pfeat, *pskip, *pskip2;
    cudaGetSymbolAddress((void**)&pfeat,  g_feat);
    cudaGetSymbolAddress((void**)&pskip,  g_skip);
    cudaGetSymbolAddress((void**)&pskip2, g_skip2);

    repack_kernel<<<(17 * NPOS + 255) / 256, 256>>>(x, cond);
    init_conv_kernel<<<(RWC * NPOS) / 256, 256>>>(init_w, init_b);
    // skip = init_skip_w @ feat + init_skip_b
    gemm64_kernel<0,0,0><<<dim3(NPOS/64, SWC/64), 256>>>(init_skip_w, pfeat, pskip,
                                                         init_skip_b, RWC);
    for (int i = 0; i < 30; i++) {
        int d = 1 << (i % 10);
        layer_res_kernel<<<dim3(NPOS/64, RWC/64), 256>>>(
            filter_w + (size_t)i * RWC * RWC * 3,
            gate_w   + (size_t)i * RWC * RWC * 3,
            fcond_w  + (size_t)i * RWC * CDC,
            gcond_w  + (size_t)i * RWC * CDC,
            4 * d);
        // feat += feat_w @ res ; skip += skip_w @ res (fused, 12 row-tiles)
        accum2_kernel<<<dim3(NPOS/64, 12), 256>>>(
            feat_w + (size_t)i * RWC * RWC,
            skip_w + (size_t)i * SWC * RWC);
    }
    // skip2 = fsw @ relu(skip) + fsb
    gemm64_kernel<1,0,0><<<dim3(NPOS/64, SWC/64), 256>>>(fsw, pskip, pskip2, fsb, SWC);
    // out = fw @ relu(skip2) + fb, stored as (B,256,W)
    gemm64_kernel<1,0,1><<<dim3(NPOS/64, SWC/64), 256>>>(fw, pskip2, (float*)d_out, fb, SWC);
}

// round 3
// speedup vs baseline: 1.0004x; 1.0004x over previous
#include <cuda_runtime.h>
#include <math.h>

#define NPOS 16384
#define NPOS_MASK 16383
#define RWC 512
#define SWC 256
#define CDC 16

// Persistent scratch (allocation-free rule: __device__ globals)
__device__ float g_feat [RWC * NPOS];   // 33.5 MB
__device__ float g_res  [RWC * NPOS];   // 33.5 MB
__device__ float g_skip [SWC * NPOS];   // 16.8 MB
__device__ float g_skip2[SWC * NPOS];   // 16.8 MB
__device__ float g_xl   [NPOS];
__device__ float g_cond [CDC * NPOS];

// ---------------------------------------------------------------------------
// Repack x (B,1,W) and cond (B,16,W) into L-layout: L = w*4 + b
// ---------------------------------------------------------------------------
__global__ void repack_kernel(const float* __restrict__ x,
                              const float* __restrict__ cond)
{
    int idx = blockIdx.x * blockDim.x + threadIdx.x;
    if (idx >= 17 * NPOS) return;
    int j = idx >> 14;            // 0..15 = cond channel, 16 = x
    int L = idx & NPOS_MASK;
    int b = L & 3, w = L >> 2;
    if (j == 16) g_xl[L] = x[b * 4096 + w];
    else         g_cond[j * NPOS + L] = cond[(b * CDC + j) * 4096 + w];
}

// ---------------------------------------------------------------------------
// Init conv: feat[c][L] = init_b[c] + sum_t init_w[c][t] * x[L + (t-1)*4]
// ---------------------------------------------------------------------------
__global__ void init_conv_kernel(const float* __restrict__ iw,
                                 const float* __restrict__ ib)
{
    int idx = blockIdx.x * blockDim.x + threadIdx.x;   // over 512*16384
    int c = idx >> 14;
    int L = idx & NPOS_MASK;
    float acc = ib[c];
    acc = fmaf(iw[c * 3 + 1], g_xl[L], acc);
    if (L >= 4)        acc = fmaf(iw[c * 3 + 0], g_xl[L - 4], acc);
    if (L < NPOS - 4)  acc = fmaf(iw[c * 3 + 2], g_xl[L + 4], acc);
    g_feat[idx] = acc;
}

// ---------------------------------------------------------------------------
// Generic tiled GEMM: C[M x NPOS] (+)= A[M x K] * B[K x NPOS] (+ bias)
// 64x64 tile, 256 threads, 4x4 register tile per thread.
// RELU_IN: relu applied to B on load. ACC: C += (bias ignored).
// TOUT: store to (B,256,W)-ordered output.
// ---------------------------------------------------------------------------
template<int RELU_IN, int ACC, int TOUT>
__global__ void __launch_bounds__(256) gemm64_kernel(
    const float* __restrict__ A, const float* __restrict__ Bm,
    float* __restrict__ C, const float* __restrict__ bias, int K)
{
    __shared__ float sA[64 * 16];   // [m][k]
    __shared__ float sB[16 * 64];   // [k][n]
    int tid = threadIdx.x;
    int tx = tid & 15, ty = tid >> 4;
    int L0 = blockIdx.x * 64;
    int m0 = blockIdx.y * 64;
    float acc[4][4] = {};

    for (int k0 = 0; k0 < K; k0 += 16) {
        {   // A tile: thread loads one float4 (row m, 4 consecutive k)
            int m = tid >> 2, kk = (tid & 3) << 2;
            *(float4*)(sA + m * 16 + kk) =
                *(const float4*)(A + (size_t)(m0 + m) * K + k0 + kk);
        }
        {   // B tile
            int kk = tid >> 4, n = (tid & 15) << 2;
            float4 v = *(const float4*)(Bm + (size_t)(k0 + kk) * NPOS + L0 + n);
            if (RELU_IN) {
                v.x = fmaxf(v.x, 0.f); v.y = fmaxf(v.y, 0.f);
                v.z = fmaxf(v.z, 0.f); v.w = fmaxf(v.w, 0.f);
            }
            *(float4*)(sB + kk * 64 + n) = v;
        }
        __syncthreads();
        #pragma unroll
        for (int kk = 0; kk < 16; kk++) {
            float4 b4 = *(float4*)(sB + kk * 64 + (tx << 2));
            float bx[4] = {b4.x, b4.y, b4.z, b4.w};
            #pragma unroll
            for (int j = 0; j < 4; j++) {
                float a = sA[(ty * 4 + j) * 16 + kk];
                #pragma unroll
                for (int i = 0; i < 4; i++)
                    acc[j][i] = fmaf(a, bx[i], acc[j][i]);
            }
        }
        __syncthreads();
    }

    #pragma unroll
    for (int j = 0; j < 4; j++) {
        int m = m0 + ty * 4 + j;
        int L = L0 + (tx << 2);
        if (ACC) {
            float4* p = (float4*)(C + (size_t)m * NPOS + L);
            float4 v = *p;
            v.x += acc[j][0]; v.y += acc[j][1];
            v.z += acc[j][2]; v.w += acc[j][3];
            *p = v;
        } else {
            float bv = (bias != nullptr) ? bias[m] : 0.f;
            if (TOUT) {
                #pragma unroll
                for (int i = 0; i < 4; i++) {
                    int Li = L + i;
                    int b = Li & 3, w = Li >> 2;
                    C[((size_t)b * SWC + m) * 4096 + w] = acc[j][i] + bv;
                }
            } else {
                float4 v;
                v.x = acc[j][0] + bv; v.y = acc[j][1] + bv;
                v.z = acc[j][2] + bv; v.w = acc[j][3] + bv;
                *(float4*)(C + (size_t)m * NPOS + L) = v;
            }
        }
    }
}

// ---------------------------------------------------------------------------
// Fused accumulate GEMM for one layer:
//   blocks with blockIdx.y <  8 : g_feat += feat_w @ g_res   (rows 0..511)
//   blocks with blockIdx.y >= 8 : g_skip += skip_w @ g_res   (rows 0..255)
// Same 64x64x16 tiling as gemm64_kernel, K = 512 fixed.
// ---------------------------------------------------------------------------
__global__ void __launch_bounds__(256) accum2_kernel(
    const float* __restrict__ Wfeat, const float* __restrict__ Wskip)
{
    __shared__ float sA[64 * 16];
    __shared__ float sB[16 * 64];
    int tid = threadIdx.x;
    int tx = tid & 15, ty = tid >> 4;
    int L0 = blockIdx.x * 64;
    int by = blockIdx.y;
    const float* A;
    float* C;
    int m0;
    if (by < 8) { A = Wfeat; C = g_feat; m0 = by * 64; }
    else        { A = Wskip; C = g_skip; m0 = (by - 8) * 64; }
    float acc[4][4] = {};

    for (int k0 = 0; k0 < RWC; k0 += 16) {
        {
            int m = tid >> 2, kk = (tid & 3) << 2;
            *(float4*)(sA + m * 16 + kk) =
                *(const float4*)(A + (size_t)(m0 + m) * RWC + k0 + kk);
        }
        {
            int kk = tid >> 4, n = (tid & 15) << 2;
            *(float4*)(sB + kk * 64 + n) =
                *(const float4*)(g_res + (size_t)(k0 + kk) * NPOS + L0 + n);
        }
        __syncthreads();
        #pragma unroll
        for (int kk = 0; kk < 16; kk++) {
            float4 b4 = *(float4*)(sB + kk * 64 + (tx << 2));
            float bx[4] = {b4.x, b4.y, b4.z, b4.w};
            #pragma unroll
            for (int j = 0; j < 4; j++) {
                float a = sA[(ty * 4 + j) * 16 + kk];
                #pragma unroll
                for (int i = 0; i < 4; i++)
                    acc[j][i] = fmaf(a, bx[i], acc[j][i]);
            }
        }
        __syncthreads();
    }

    #pragma unroll
    for (int j = 0; j < 4; j++) {
        int m = m0 + ty * 4 + j;
        int L = L0 + (tx << 2);
        float4* p = (float4*)(C + (size_t)m * NPOS + L);
        float4 v = *p;
        v.x += acc[j][0]; v.y += acc[j][1];
        v.z += acc[j][2]; v.w += acc[j][3];
        *p = v;
    }
}

// ---------------------------------------------------------------------------
// Layer residual kernel: fused filter+gate dilated conv + cond + gated act.
// K dimension = 512 channels x 3 taps (chunked 16 ch = 48 kk) + 16 cond ch.
// Tap t reads feat[c][L + (t-1)*sh], sh = 4*d; OOB -> 0 (== conv padding).
// ---------------------------------------------------------------------------
__global__ void __launch_bounds__(256) layer_res_kernel(
    const float* __restrict__ Wf, const float* __restrict__ Wg,
    const float* __restrict__ Wfc, const float* __restrict__ Wgc,
    int sh)
{
    __shared__ float sWf[64 * 48];  // [m][kk], kk = c_local*3 + t
    __shared__ float sWg[64 * 48];
    __shared__ float sX [48 * 64];  // [kk][n]
    int tid = threadIdx.x;
    int tx = tid & 15, ty = tid >> 4;
    int L0 = blockIdx.x * 64;
    int o0 = blockIdx.y * 64;
    float af[4][4] = {};
    float ag[4][4] = {};

    for (int c0 = 0; c0 < RWC; c0 += 16) {
        // weights: 64 rows x 48 (contiguous 48-float run per output channel)
        #pragma unroll
        for (int r = 0; r < 3; r++) {
            int e = tid + r * 256;         // float4 index 0..767
            int m = e / 12;
            int kk = (e - m * 12) * 4;
            size_t off = (size_t)(o0 + m) * 1536 + c0 * 3 + kk;
            *(float4*)(sWf + m * 48 + kk) = *(const float4*)(Wf + off);
            *(float4*)(sWg + m * 48 + kk) = *(const float4*)(Wg + off);
        }
        // X: 48 rows x 64, row kk=(cl,t) is feat[c0+cl] shifted by (t-1)*sh
        #pragma unroll
        for (int r = 0; r < 3; r++) {
            int e = tid + r * 256;
            int kk = e >> 4;
            int n4 = (e & 15) << 2;
            int cl = kk / 3;
            int t  = kk - cl * 3;
            int pos = L0 + n4 + (t - 1) * sh;
            float4 v = make_float4(0.f, 0.f, 0.f, 0.f);
            if (pos >= 0 && pos < NPOS)
                v = *(const float4*)(g_feat + (size_t)(c0 + cl) * NPOS + pos);
            *(float4*)(sX + kk * 64 + n4) = v;
        }
        __syncthreads();
        #pragma unroll 8
        for (int kk = 0; kk < 48; kk++) {
            float4 b4 = *(float4*)(sX + kk * 64 + (tx << 2));
            float bx[4] = {b4.x, b4.y, b4.z, b4.w};
            #pragma unroll
            for (int j = 0; j < 4; j++) {
                float wf = sWf[(ty * 4 + j) * 48 + kk];
                float wg = sWg[(ty * 4 + j) * 48 + kk];
                #pragma unroll
                for (int i = 0; i < 4; i++) {
                    af[j][i] = fmaf(wf, bx[i], af[j][i]);
                    ag[j][i] = fmaf(wg, bx[i], ag[j][i]);
                }
            }
        }
        __syncthreads();
    }

    // cond contribution: 16 extra K rows (center tap only, no shift)
    {
        int m = tid >> 2, kk = (tid & 3) << 2;
        *(float4*)(sWf + m * 16 + kk) = *(const float4*)(Wfc + (size_t)(o0 + m) * 16 + kk);
        *(float4*)(sWg + m * 16 + kk) = *(const float4*)(Wgc + (size_t)(o0 + m) * 16 + kk);
        int kb = tid >> 4, n = (tid & 15) << 2;
        *(float4*)(sX + kb * 64 + n) = *(const float4*)(g_cond + (size_t)kb * NPOS + L0 + n);
    }
    __syncthreads();
    #pragma unroll
    for (int kk = 0; kk < 16; kk++) {
        float4 b4 = *(float4*)(sX + kk * 64 + (tx << 2));
        float bx[4] = {b4.x, b4.y, b4.z, b4.w};
        #pragma unroll
        for (int j = 0; j < 4; j++) {
            float wf = sWf[(ty * 4 + j) * 16 + kk];
            float wg = sWg[(ty * 4 + j) * 16 + kk];
            #pragma unroll
            for (int i = 0; i < 4; i++) {
                af[j][i] = fmaf(wf, bx[i], af[j][i]);
                ag[j][i] = fmaf(wg, bx[i], ag[j][i]);
            }
        }
    }

    // epilogue: residual = sigmoid(f) * tanh(g)
    #pragma unroll
    for (int j = 0; j < 4; j++) {
        int o = o0 + ty * 4 + j;
        float4 v;
        float* vv = &v.x;
        #pragma unroll
        for (int i = 0; i < 4; i++) {
            float f = af[j][i], g = ag[j][i];
            float s = 1.f / (1.f + expf(-f));
            vv[i] = s * tanhf(g);
        }
        *(float4*)(g_res + (size_t)o * NPOS + L0 + (tx << 2)) = v;
    }
}

// ---------------------------------------------------------------------------
extern "C" void kernel_launch(void* const* d_in, const int* in_sizes, int n_in,
                              void* d_out, int out_size)
{
    const float* x           = (const float*)d_in[0];
    const float* cond        = (const float*)d_in[1];
    const float* init_w      = (const float*)d_in[2];
    const float* init_b      = (const float*)d_in[3];
    const float* init_skip_w = (const float*)d_in[4];
    const float* init_skip_b = (const float*)d_in[5];
    const float* filter_w    = (const float*)d_in[6];
    const float* gate_w      = (const float*)d_in[7];
    const float* skip_w      = (const float*)d_in[8];
    const float* feat_w      = (const float*)d_in[9];
    const float* fcond_w     = (const float*)d_in[10];
    const float* gcond_w     = (const float*)d_in[11];
    const float* fsw         = (const float*)d_in[12];
    const float* fsb         = (const float*)d_in[13];
    const float* fw          = (const float*)d_in[14];
    const float* fb          = (const float*)d_in[15];

    float *pfeat, *pskip, *pskip2;
    cudaGetSymbolAddress((void**)&pfeat,  g_feat);
    cudaGetSymbolAddress((void**)&pskip,  g_skip);
    cudaGetSymbolAddress((void**)&pskip2, g_skip2);

    repack_kernel<<<(17 * NPOS + 255) / 256, 256>>>(x, cond);
    init_conv_kernel<<<(RWC * NPOS) / 256, 256>>>(init_w, init_b);
    // skip = init_skip_w @ feat + init_skip_b
    gemm64_kernel<0,0,0><<<dim3(NPOS/64, SWC/64), 256>>>(init_skip_w, pfeat, pskip,
                                                         init_skip_b, RWC);
    for (int i = 0; i < 30; i++) {
        int d = 1 << (i % 10);
        layer_res_kernel<<<dim3(NPOS/64, RWC/64), 256>>>(
            filter_w + (size_t)i * RWC * RWC * 3,
            gate_w   + (size_t)i * RWC * RWC * 3,
            fcond_w  + (size_t)i * RWC * CDC,
            gcond_w  + (size_t)i * RWC * CDC,
            4 * d);
        // feat += feat_w @ res ; skip += skip_w @ res (fused, 12 row-tiles)
        accum2_kernel<<<dim3(NPOS/64, 12), 256>>>(
            feat_w + (size_t)i * RWC * RWC,
            skip_w + (size_t)i * SWC * RWC);
    }
    // skip2 = fsw @ relu(skip) + fsb
    gemm64_kernel<1,0,0><<<dim3(NPOS/64, SWC/64), 256>>>(fsw, pskip, pskip2, fsb, SWC);
    // out = fw @ relu(skip2) + fb, stored as (B,256,W)
    gemm64_kernel<1,0,1><<<dim3(NPOS/64, SWC/64), 256>>>(fw, pskip2, (float*)d_out, fb, SWC);
}